// round 1
// baseline (speedup 1.0000x reference)
#include <cuda_runtime.h>
#include <cstdint>
#include <cstddef>

#define NN 4096
#define DD 128
#define EPS 1e-12f

// Scratch (allocation-free rule: __device__ globals)
__device__ float g_att[(size_t)NN * NN];   // 64 MB attention accumulator
__device__ float g_feat[NN * DD];          // W @ activities
__device__ float g_inv[NN];                // 1/(rowsum+eps)
__device__ int   g_is64;                   // index dtype flag

// ---------------------------------------------------------------------------
// Detect whether index arrays are int64 or int32.
// Values are in [0, 4096). If int64 (little-endian), every odd 32-bit word of
// the first 64 entries is 0. If int32, those words are random indices — the
// probability of 64 of them all being zero is (1/4096)^~64 ≈ 0.
// ---------------------------------------------------------------------------
__global__ void detect_kernel(const unsigned int* __restrict__ w) {
    if (threadIdx.x == 0) {
        int is64 = 1;
        for (int i = 0; i < 64; i++) {
            if (w[2 * i + 1] != 0u) { is64 = 0; break; }
        }
        g_is64 = is64;
    }
}

// ---------------------------------------------------------------------------
// Zero the 64 MB attention matrix (float4 stores, 16384 blocks x 256 thr)
// ---------------------------------------------------------------------------
__global__ void zero_att_kernel() {
    size_t i = (size_t)blockIdx.x * blockDim.x + threadIdx.x;
    ((float4*)g_att)[i] = make_float4(0.f, 0.f, 0.f, 0.f);
}

// ---------------------------------------------------------------------------
// Edge pass: warp per edge. lane l handles floats [4l, 4l+4).
// dist = ||A[c] + case[e] - A[t]||; att[t][c] += exp(-dist)
// ---------------------------------------------------------------------------
__global__ void edge_kernel(const void* __restrict__ cur_,
                            const void* __restrict__ tgt_,
                            const float* __restrict__ A,
                            const float* __restrict__ cases,
                            int E) {
    int e = blockIdx.x * 8 + threadIdx.y;
    if (e >= E) return;
    int lane = threadIdx.x;

    int c, t;
    if (g_is64) {
        c = (int)((const long long*)cur_)[e];
        t = (int)((const long long*)tgt_)[e];
    } else {
        c = ((const int*)cur_)[e];
        t = ((const int*)tgt_)[e];
    }

    float4 h4 = ((const float4*)(A + (size_t)c * DD))[lane];
    float4 t4 = ((const float4*)(A + (size_t)t * DD))[lane];
    float4 c4 = ((const float4*)(cases + (size_t)e * DD))[lane];

    float dx = h4.x + c4.x - t4.x;
    float dy = h4.y + c4.y - t4.y;
    float dz = h4.z + c4.z - t4.z;
    float dw = h4.w + c4.w - t4.w;
    float s = dx * dx + dy * dy + dz * dz + dw * dw;

#pragma unroll
    for (int o = 16; o > 0; o >>= 1)
        s += __shfl_xor_sync(0xffffffffu, s, o);

    if (lane == 0) {
        float v = expf(-sqrtf(s));
        atomicAdd(&g_att[(size_t)t * NN + c], v);
    }
}

// ---------------------------------------------------------------------------
// Row sums -> inverse norm. Warp per row.
// ---------------------------------------------------------------------------
__global__ void rowsum_kernel() {
    int row = blockIdx.x * 8 + threadIdx.y;
    int lane = threadIdx.x;
    const float4* p = (const float4*)(g_att + (size_t)row * NN);
    float s = 0.f;
#pragma unroll 4
    for (int i = lane; i < NN / 4; i += 32) {
        float4 v = p[i];
        s += v.x + v.y + v.z + v.w;
    }
#pragma unroll
    for (int o = 16; o > 0; o >>= 1)
        s += __shfl_xor_sync(0xffffffffu, s, o);
    if (lane == 0) g_inv[row] = 1.0f / (s + EPS);
}

// ---------------------------------------------------------------------------
// GEMM 1: g_feat = W @ A   (W [4096,4096], A [4096,128])
// Block: 32 rows x 128 cols, 256 threads (16x16), thread tile 2x8, BK=32.
// ---------------------------------------------------------------------------
__global__ void gemm_feat_kernel(const float* __restrict__ Wm,
                                 const float* __restrict__ A) {
    __shared__ float Ws[32][33];
    __shared__ float Bs[32][128];
    int tid = threadIdx.x;
    int tx = tid & 15;       // col group: cols [tx*8, tx*8+8)
    int ty = tid >> 4;       // row group: rows [ty*2, ty*2+2)
    int row0 = blockIdx.x * 32;

    float acc[2][8];
#pragma unroll
    for (int i = 0; i < 2; i++)
#pragma unroll
        for (int j = 0; j < 8; j++) acc[i][j] = 0.f;

    int lr = tid >> 3;          // 0..31
    int lc = (tid & 7) * 4;     // 0..28

    for (int k0 = 0; k0 < NN; k0 += 32) {
        float4 w4 = *(const float4*)&Wm[(size_t)(row0 + lr) * NN + k0 + lc];
        Ws[lr][lc] = w4.x; Ws[lr][lc + 1] = w4.y;
        Ws[lr][lc + 2] = w4.z; Ws[lr][lc + 3] = w4.w;
#pragma unroll
        for (int i = 0; i < 4; i++) {
            int f = tid + i * 256;          // float4 index in 32x128 tile
            int r = f >> 5;
            int cc = (f & 31) * 4;
            *(float4*)&Bs[r][cc] = *(const float4*)&A[(size_t)(k0 + r) * DD + cc];
        }
        __syncthreads();
#pragma unroll
        for (int k = 0; k < 32; k++) {
            float w0 = Ws[ty * 2][k];
            float w1 = Ws[ty * 2 + 1][k];
            float4 b0 = *(float4*)&Bs[k][tx * 8];
            float4 b1 = *(float4*)&Bs[k][tx * 8 + 4];
            acc[0][0] += w0 * b0.x; acc[0][1] += w0 * b0.y;
            acc[0][2] += w0 * b0.z; acc[0][3] += w0 * b0.w;
            acc[0][4] += w0 * b1.x; acc[0][5] += w0 * b1.y;
            acc[0][6] += w0 * b1.z; acc[0][7] += w0 * b1.w;
            acc[1][0] += w1 * b0.x; acc[1][1] += w1 * b0.y;
            acc[1][2] += w1 * b0.z; acc[1][3] += w1 * b0.w;
            acc[1][4] += w1 * b1.x; acc[1][5] += w1 * b1.y;
            acc[1][6] += w1 * b1.z; acc[1][7] += w1 * b1.w;
        }
        __syncthreads();
    }
#pragma unroll
    for (int i = 0; i < 2; i++) {
        int r = row0 + ty * 2 + i;
        float4 o0 = make_float4(acc[i][0], acc[i][1], acc[i][2], acc[i][3]);
        float4 o1 = make_float4(acc[i][4], acc[i][5], acc[i][6], acc[i][7]);
        *(float4*)&g_feat[r * DD + tx * 8] = o0;
        *(float4*)&g_feat[r * DD + tx * 8 + 4] = o1;
    }
}

// ---------------------------------------------------------------------------
// GEMM 2: out = diag(g_inv) * (g_att @ g_feat) + g_feat
// ---------------------------------------------------------------------------
__global__ void gemm_out_kernel(float* __restrict__ out) {
    __shared__ float Ws[32][33];
    __shared__ float Bs[32][128];
    int tid = threadIdx.x;
    int tx = tid & 15;
    int ty = tid >> 4;
    int row0 = blockIdx.x * 32;

    float acc[2][8];
#pragma unroll
    for (int i = 0; i < 2; i++)
#pragma unroll
        for (int j = 0; j < 8; j++) acc[i][j] = 0.f;

    int lr = tid >> 3;
    int lc = (tid & 7) * 4;

    for (int k0 = 0; k0 < NN; k0 += 32) {
        float4 w4 = *(const float4*)&g_att[(size_t)(row0 + lr) * NN + k0 + lc];
        Ws[lr][lc] = w4.x; Ws[lr][lc + 1] = w4.y;
        Ws[lr][lc + 2] = w4.z; Ws[lr][lc + 3] = w4.w;
#pragma unroll
        for (int i = 0; i < 4; i++) {
            int f = tid + i * 256;
            int r = f >> 5;
            int cc = (f & 31) * 4;
            *(float4*)&Bs[r][cc] = *(const float4*)&g_feat[(size_t)(k0 + r) * DD + cc];
        }
        __syncthreads();
#pragma unroll
        for (int k = 0; k < 32; k++) {
            float w0 = Ws[ty * 2][k];
            float w1 = Ws[ty * 2 + 1][k];
            float4 b0 = *(float4*)&Bs[k][tx * 8];
            float4 b1 = *(float4*)&Bs[k][tx * 8 + 4];
            acc[0][0] += w0 * b0.x; acc[0][1] += w0 * b0.y;
            acc[0][2] += w0 * b0.z; acc[0][3] += w0 * b0.w;
            acc[0][4] += w0 * b1.x; acc[0][5] += w0 * b1.y;
            acc[0][6] += w0 * b1.z; acc[0][7] += w0 * b1.w;
            acc[1][0] += w1 * b0.x; acc[1][1] += w1 * b0.y;
            acc[1][2] += w1 * b0.z; acc[1][3] += w1 * b0.w;
            acc[1][4] += w1 * b1.x; acc[1][5] += w1 * b1.y;
            acc[1][6] += w1 * b1.z; acc[1][7] += w1 * b1.w;
        }
        __syncthreads();
    }
#pragma unroll
    for (int i = 0; i < 2; i++) {
        int r = row0 + ty * 2 + i;
        float inv = g_inv[r];
        int cbase = r * DD + tx * 8;
        float4 f0 = *(const float4*)&g_feat[cbase];
        float4 f1 = *(const float4*)&g_feat[cbase + 4];
        float4 o0 = make_float4(acc[i][0] * inv + f0.x, acc[i][1] * inv + f0.y,
                                acc[i][2] * inv + f0.z, acc[i][3] * inv + f0.w);
        float4 o1 = make_float4(acc[i][4] * inv + f1.x, acc[i][5] * inv + f1.y,
                                acc[i][6] * inv + f1.z, acc[i][7] * inv + f1.w);
        *(float4*)&out[cbase] = o0;
        *(float4*)&out[cbase + 4] = o1;
    }
}

// ---------------------------------------------------------------------------
extern "C" void kernel_launch(void* const* d_in, const int* in_sizes, int n_in,
                              void* d_out, int out_size) {
    const void* cur = d_in[0];
    const void* tgt = d_in[1];
    const float* A = (const float*)d_in[2];
    const float* cases = (const float*)d_in[3];
    const float* W = (const float*)d_in[4];
    float* out = (float*)d_out;

    int E = in_sizes[3] / DD;   // dtype-independent (cases is E*D floats)

    detect_kernel<<<1, 32>>>((const unsigned int*)cur);
    zero_att_kernel<<<((size_t)NN * NN / 4) / 256, 256>>>();
    edge_kernel<<<(E + 7) / 8, dim3(32, 8)>>>(cur, tgt, A, cases, E);
    rowsum_kernel<<<NN / 8, dim3(32, 8)>>>();
    gemm_feat_kernel<<<NN / 32, 256>>>(W, A);
    gemm_out_kernel<<<NN / 32, 256>>>(out);
}

// round 4
// speedup vs baseline: 3.0071x; 3.0071x over previous
#include <cuda_runtime.h>
#include <cuda_bf16.h>
#include <cstdint>
#include <cstddef>

#define NN 4096
#define DD 128
#define EPS 1e-12f

// ---------------- scratch (__device__ globals; no allocs allowed) ----------
__device__ float g_att[(size_t)NN * NN];          // 64 MB attention accumulator
__device__ float g_feat[NN * DD];                 // W @ activities
__device__ float g_acc[NN * DD];                  // att @ feat (unnormalized)
__device__ float g_rowsum[NN];
__device__ __nv_bfloat16 g_Bh[DD * NN], g_Bl[DD * NN];   // activities^T split [N][K]
__device__ __nv_bfloat16 g_Fh[DD * NN], g_Fl[DD * NN];   // feat^T split [N][K]
__device__ int g_is64;

// ---------------------------------------------------------------------------
__global__ void detect_kernel(const unsigned int* __restrict__ w) {
    if (threadIdx.x == 0) {
        int is64 = 1;
        for (int i = 0; i < 64; i++)
            if (w[2 * i + 1] != 0u) { is64 = 0; break; }
        g_is64 = is64;
    }
}

// ---------------------------------------------------------------------------
// Edge pass: warp per edge.
// ---------------------------------------------------------------------------
__global__ void edge_kernel(const void* __restrict__ cur_,
                            const void* __restrict__ tgt_,
                            const float* __restrict__ A,
                            const float* __restrict__ cases,
                            int E) {
    int e = blockIdx.x * 8 + threadIdx.y;
    if (e >= E) return;
    int lane = threadIdx.x;
    int c, t;
    if (g_is64) {
        c = (int)((const long long*)cur_)[e];
        t = (int)((const long long*)tgt_)[e];
    } else {
        c = ((const int*)cur_)[e];
        t = ((const int*)tgt_)[e];
    }
    float4 h4 = ((const float4*)(A + (size_t)c * DD))[lane];
    float4 t4 = ((const float4*)(A + (size_t)t * DD))[lane];
    float4 c4 = ((const float4*)(cases + (size_t)e * DD))[lane];
    float dx = h4.x + c4.x - t4.x;
    float dy = h4.y + c4.y - t4.y;
    float dz = h4.z + c4.z - t4.z;
    float dw = h4.w + c4.w - t4.w;
    float s = dx * dx + dy * dy + dz * dz + dw * dw;
#pragma unroll
    for (int o = 16; o > 0; o >>= 1) s += __shfl_xor_sync(0xffffffffu, s, o);
    if (lane == 0) atomicAdd(&g_att[(size_t)t * NN + c], expf(-sqrtf(s)));
}

// ---------------------------------------------------------------------------
// Transpose + bf16 split: src [4096,128] fp32 -> Bh,Bl [128,4096] bf16 ([N][K])
// ---------------------------------------------------------------------------
__global__ void prep_split_kernel(const float* __restrict__ src,
                                  __nv_bfloat16* __restrict__ Bh,
                                  __nv_bfloat16* __restrict__ Bl) {
    __shared__ float tile[32][33];
    int k0 = blockIdx.x * 32, n0 = blockIdx.y * 32;
    int tx = threadIdx.x, ty = threadIdx.y;
#pragma unroll
    for (int i = 0; i < 4; i++)
        tile[ty + i * 8][tx] = src[(size_t)(k0 + ty + i * 8) * DD + n0 + tx];
    __syncthreads();
#pragma unroll
    for (int i = 0; i < 4; i++) {
        float x = tile[tx][ty + i * 8];
        __nv_bfloat16 h = __float2bfloat16_rn(x);
        __nv_bfloat16 l = __float2bfloat16_rn(x - __bfloat162float(h));
        size_t o = (size_t)(n0 + ty + i * 8) * NN + k0 + tx;
        Bh[o] = h;
        Bl[o] = l;
    }
}

// ---------------------------------------------------------------------------
// Warp-MMA split-bf16 GEMM:  outacc[m0:m0+128][0:128] += A_tile @ B^T
//   Amat [4096,4096] fp32 row-major; Bh/Bl [128][4096] bf16 ([N][K]).
//   grid = 32 M-tiles x 4 K-splits; block 256 thr (8 warps, 4M x 2N).
//   Per warp: 32M x 64N = 2 x 8 m16n8k16 tiles, 3 MMAs per tile (split terms).
//   Optionally accumulates row-sums of Amat into rowsum[].
// ---------------------------------------------------------------------------
#define A_PITCH 72          // bf16 elements per row (+8 pad: conflict-free frags)
#define PITCHB (A_PITCH * 2)
#define SM_AH 0
#define SM_AL (128 * PITCHB)
#define SM_BH (2 * 128 * PITCHB)
#define SM_BL (3 * 128 * PITCHB)
#define SMEM_GEMM (4 * 128 * PITCHB)   // 73728 B

__device__ __forceinline__ void mma_bf16(float* c, const uint32_t* a, const uint32_t* b) {
    asm volatile(
        "mma.sync.aligned.m16n8k16.row.col.f32.bf16.bf16.f32 "
        "{%0,%1,%2,%3}, {%4,%5,%6,%7}, {%8,%9}, {%0,%1,%2,%3};"
        : "+f"(c[0]), "+f"(c[1]), "+f"(c[2]), "+f"(c[3])
        : "r"(a[0]), "r"(a[1]), "r"(a[2]), "r"(a[3]), "r"(b[0]), "r"(b[1]));
}

__global__ __launch_bounds__(256, 1)
void gemm_mma_kernel(const float* __restrict__ Amat,
                     const __nv_bfloat16* __restrict__ Bh,
                     const __nv_bfloat16* __restrict__ Bl,
                     float* __restrict__ outacc,
                     float* __restrict__ rowsum, int do_rowsum) {
    extern __shared__ char smem[];
    const int tid = threadIdx.x;
    const int wid = tid >> 5, lane = tid & 31;
    const int warp_m = wid >> 1, warp_n = wid & 1;
    const int lr = lane >> 2, lc = lane & 3;
    const int m0 = (blockIdx.x >> 2) * 128;
    const int kbase = (blockIdx.x & 3) * 1024;

    const int a_row = tid >> 4;          // + i*16, i<8  -> rows 0..127
    const int a_c4 = tid & 15;           // float4 slot in 64-float row

    float acc[2][8][4];
#pragma unroll
    for (int i = 0; i < 2; i++)
#pragma unroll
        for (int j = 0; j < 8; j++)
#pragma unroll
            for (int q = 0; q < 4; q++) acc[i][j][q] = 0.f;

    float rs[8];
#pragma unroll
    for (int i = 0; i < 8; i++) rs[i] = 0.f;

    for (int ch = 0; ch < 16; ch++) {
        int k0 = kbase + ch * 64;
        // ---- global loads into registers ----
        float4 av[8];
#pragma unroll
        for (int i = 0; i < 8; i++)
            av[i] = *(const float4*)&Amat[(size_t)(m0 + a_row + i * 16) * NN + k0 + a_c4 * 4];
        // B tile: 128 rows x 128 bytes = 1024 uint4; 4 per thread
        uint4 bhv[4], blv[4];
#pragma unroll
        for (int i = 0; i < 4; i++) {
            int idx = tid + i * 256;          // 0..1023
            int n = idx >> 3, q = idx & 7;
            size_t byt = ((size_t)n * NN + k0) * 2 + q * 16;
            bhv[i] = *(const uint4*)((const char*)Bh + byt);
            blv[i] = *(const uint4*)((const char*)Bl + byt);
        }
        if (ch > 0) __syncthreads();          // previous MMA done before overwrite
        // ---- convert A to split bf16, store to smem ----
#pragma unroll
        for (int i = 0; i < 8; i++) {
            float4 v = av[i];
            if (do_rowsum) rs[i] += (v.x + v.y) + (v.z + v.w);
            __nv_bfloat16 h0 = __float2bfloat16_rn(v.x);
            __nv_bfloat16 h1 = __float2bfloat16_rn(v.y);
            __nv_bfloat16 h2 = __float2bfloat16_rn(v.z);
            __nv_bfloat16 h3 = __float2bfloat16_rn(v.w);
            __nv_bfloat16 l0 = __float2bfloat16_rn(v.x - __bfloat162float(h0));
            __nv_bfloat16 l1 = __float2bfloat16_rn(v.y - __bfloat162float(h1));
            __nv_bfloat16 l2 = __float2bfloat16_rn(v.z - __bfloat162float(h2));
            __nv_bfloat16 l3 = __float2bfloat16_rn(v.w - __bfloat162float(h3));
            uint2 hp, lp;
            hp.x = ((uint32_t)__bfloat16_as_ushort(h1) << 16) | __bfloat16_as_ushort(h0);
            hp.y = ((uint32_t)__bfloat16_as_ushort(h3) << 16) | __bfloat16_as_ushort(h2);
            lp.x = ((uint32_t)__bfloat16_as_ushort(l1) << 16) | __bfloat16_as_ushort(l0);
            lp.y = ((uint32_t)__bfloat16_as_ushort(l3) << 16) | __bfloat16_as_ushort(l2);
            uint32_t off = (uint32_t)(a_row + i * 16) * PITCHB + a_c4 * 8;
            *(uint2*)(smem + SM_AH + off) = hp;
            *(uint2*)(smem + SM_AL + off) = lp;
        }
        // ---- store B tiles ([N][K] rows of 64 bf16 = 128 B, pitch 144 B) ----
#pragma unroll
        for (int i = 0; i < 4; i++) {
            int idx = tid + i * 256;
            int n = idx >> 3, q = idx & 7;
            uint32_t off = (uint32_t)n * PITCHB + q * 16;
            *(uint4*)(smem + SM_BH + off) = bhv[i];
            *(uint4*)(smem + SM_BL + off) = blv[i];
        }
        __syncthreads();
        // ---- MMA over 4 k16 steps ----
#pragma unroll
        for (int k16 = 0; k16 < 4; k16++) {
            uint32_t a_h[2][4], a_l[2][4];
#pragma unroll
            for (int mt = 0; mt < 2; mt++) {
                uint32_t base = (uint32_t)(warp_m * 32 + mt * 16 + lr) * PITCHB
                                + k16 * 32 + lc * 4;
                a_h[mt][0] = *(const uint32_t*)(smem + SM_AH + base);
                a_h[mt][1] = *(const uint32_t*)(smem + SM_AH + base + 8 * PITCHB);
                a_h[mt][2] = *(const uint32_t*)(smem + SM_AH + base + 16);
                a_h[mt][3] = *(const uint32_t*)(smem + SM_AH + base + 8 * PITCHB + 16);
                a_l[mt][0] = *(const uint32_t*)(smem + SM_AL + base);
                a_l[mt][1] = *(const uint32_t*)(smem + SM_AL + base + 8 * PITCHB);
                a_l[mt][2] = *(const uint32_t*)(smem + SM_AL + base + 16);
                a_l[mt][3] = *(const uint32_t*)(smem + SM_AL + base + 8 * PITCHB + 16);
            }
#pragma unroll
            for (int nt = 0; nt < 8; nt++) {
                uint32_t b_h[2], b_l[2];
                uint32_t base = (uint32_t)(warp_n * 64 + nt * 8 + lr) * PITCHB
                                + k16 * 32 + lc * 4;
                b_h[0] = *(const uint32_t*)(smem + SM_BH + base);
                b_h[1] = *(const uint32_t*)(smem + SM_BH + base + 16);
                b_l[0] = *(const uint32_t*)(smem + SM_BL + base);
                b_l[1] = *(const uint32_t*)(smem + SM_BL + base + 16);
#pragma unroll
                for (int mt = 0; mt < 2; mt++) {
                    mma_bf16(acc[mt][nt], a_h[mt], b_h);
                    mma_bf16(acc[mt][nt], a_h[mt], b_l);
                    mma_bf16(acc[mt][nt], a_l[mt], b_h);
                }
            }
        }
    }

    if (do_rowsum) {
#pragma unroll
        for (int i = 0; i < 8; i++)
            atomicAdd(&rowsum[m0 + a_row + i * 16], rs[i]);
    }

    // ---- write accumulators (split-K partials -> atomicAdd) ----
#pragma unroll
    for (int mt = 0; mt < 2; mt++) {
#pragma unroll
        for (int nt = 0; nt < 8; nt++) {
            int row = m0 + warp_m * 32 + mt * 16 + lr;
            int col = warp_n * 64 + nt * 8 + lc * 2;
            atomicAdd(&outacc[(size_t)row * DD + col], acc[mt][nt][0]);
            atomicAdd(&outacc[(size_t)row * DD + col + 1], acc[mt][nt][1]);
            atomicAdd(&outacc[(size_t)(row + 8) * DD + col], acc[mt][nt][2]);
            atomicAdd(&outacc[(size_t)(row + 8) * DD + col + 1], acc[mt][nt][3]);
        }
    }
}

// ---------------------------------------------------------------------------
// out = g_acc * 1/(rowsum+eps) + g_feat
// ---------------------------------------------------------------------------
__global__ void final_out_kernel(float* __restrict__ out) {
    int i = blockIdx.x * 256 + threadIdx.x;   // float4 index; 131072 total
    int r = i >> 5;
    float inv = 1.0f / (g_rowsum[r] + EPS);
    float4 a = ((const float4*)g_acc)[i];
    float4 f = ((const float4*)g_feat)[i];
    ((float4*)out)[i] = make_float4(a.x * inv + f.x, a.y * inv + f.y,
                                    a.z * inv + f.z, a.w * inv + f.w);
}

// ---------------------------------------------------------------------------
extern "C" void kernel_launch(void* const* d_in, const int* in_sizes, int n_in,
                              void* d_out, int out_size) {
    const void* cur = d_in[0];
    const void* tgt = d_in[1];
    const float* A = (const float*)d_in[2];
    const float* cases = (const float*)d_in[3];
    const float* W = (const float*)d_in[4];
    float* out = (float*)d_out;
    int E = in_sizes[3] / DD;

    cudaFuncSetAttribute(gemm_mma_kernel,
                         cudaFuncAttributeMaxDynamicSharedMemorySize, SMEM_GEMM);

    float *p_att, *p_feat, *p_acc, *p_rowsum;
    __nv_bfloat16 *p_Bh, *p_Bl, *p_Fh, *p_Fl;
    cudaGetSymbolAddress((void**)&p_att, g_att);
    cudaGetSymbolAddress((void**)&p_feat, g_feat);
    cudaGetSymbolAddress((void**)&p_acc, g_acc);
    cudaGetSymbolAddress((void**)&p_rowsum, g_rowsum);
    cudaGetSymbolAddress((void**)&p_Bh, g_Bh);
    cudaGetSymbolAddress((void**)&p_Bl, g_Bl);
    cudaGetSymbolAddress((void**)&p_Fh, g_Fh);
    cudaGetSymbolAddress((void**)&p_Fl, g_Fl);

    cudaMemsetAsync(p_att, 0, (size_t)NN * NN * sizeof(float));
    cudaMemsetAsync(p_feat, 0, (size_t)NN * DD * sizeof(float));
    cudaMemsetAsync(p_acc, 0, (size_t)NN * DD * sizeof(float));
    cudaMemsetAsync(p_rowsum, 0, NN * sizeof(float));

    detect_kernel<<<1, 32>>>((const unsigned int*)cur);
    prep_split_kernel<<<dim3(NN / 32, DD / 32), dim3(32, 8)>>>(A, p_Bh, p_Bl);
    edge_kernel<<<(E + 7) / 8, dim3(32, 8)>>>(cur, tgt, A, cases, E);
    gemm_mma_kernel<<<128, 256, SMEM_GEMM>>>(W, p_Bh, p_Bl, p_feat, p_rowsum, 0);
    prep_split_kernel<<<dim3(NN / 32, DD / 32), dim3(32, 8)>>>(p_feat, p_Fh, p_Fl);
    gemm_mma_kernel<<<128, 256, SMEM_GEMM>>>(p_att, p_Fh, p_Fl, p_acc, p_rowsum, 1);
    final_out_kernel<<<512, 256>>>(out);
}

// round 5
// speedup vs baseline: 3.2978x; 1.0967x over previous
#include <cuda_runtime.h>
#include <cuda_bf16.h>
#include <cstdint>
#include <cstddef>

#define NN 4096
#define DD 128
#define EPS 1e-12f
#define SLOTS 512            // per-row edge slots (mean 244, 17-sigma safe)

// ---------------- scratch (__device__ globals; no allocs allowed) ----------
__device__ float g_feat[NN * DD];                       // W @ activities (fp32)
__device__ __nv_bfloat16 g_featbf[NN * DD];             // bf16 copy for SpMM gathers
__device__ __nv_bfloat16 g_Abf[NN * DD];                // activities bf16 (edge gathers)
__device__ __nv_bfloat16 g_Bh[DD * NN], g_Bl[DD * NN];  // activities^T split [N][K]
__device__ float2 g_ent[(size_t)NN * SLOTS];            // (col,val) per row, 16 MB
__device__ int g_cursor[NN];
__device__ int g_is64;

// ---------------------------------------------------------------------------
__global__ void detect_kernel(const unsigned int* __restrict__ w) {
    if (threadIdx.x == 0) {
        int is64 = 1;
        for (int i = 0; i < 64; i++)
            if (w[2 * i + 1] != 0u) { is64 = 0; break; }
        g_is64 = is64;
    }
}

// ---------------------------------------------------------------------------
// prep: A [4096,128] fp32 -> g_Bh/g_Bl [128][4096] (transposed split, GEMM B)
//                         -> g_Abf [4096,128] bf16 (edge gathers)
// ---------------------------------------------------------------------------
__global__ void prep_kernel(const float* __restrict__ src) {
    __shared__ float tile[32][33];
    int k0 = blockIdx.x * 32, n0 = blockIdx.y * 32;
    int tx = threadIdx.x, ty = threadIdx.y;
#pragma unroll
    for (int i = 0; i < 4; i++) {
        size_t idx = (size_t)(k0 + ty + i * 8) * DD + n0 + tx;
        float v = src[idx];
        tile[ty + i * 8][tx] = v;
        g_Abf[idx] = __float2bfloat16_rn(v);
    }
    __syncthreads();
#pragma unroll
    for (int i = 0; i < 4; i++) {
        float x = tile[tx][ty + i * 8];
        __nv_bfloat16 h = __float2bfloat16_rn(x);
        __nv_bfloat16 l = __float2bfloat16_rn(x - __bfloat162float(h));
        size_t o = (size_t)(n0 + ty + i * 8) * NN + k0 + tx;
        g_Bh[o] = h;
        g_Bl[o] = l;
    }
}

// ---------------------------------------------------------------------------
// Edge pass: warp per edge; A gathers in bf16 (halves L2 traffic).
// Emits (col, exp(-dist)) into row-t slot list.
// ---------------------------------------------------------------------------
__global__ void edge_kernel(const void* __restrict__ cur_,
                            const void* __restrict__ tgt_,
                            const float* __restrict__ cases,
                            int E) {
    int e = blockIdx.x * 8 + threadIdx.y;
    if (e >= E) return;
    int lane = threadIdx.x;
    int c, t;
    if (g_is64) {
        c = (int)((const long long*)cur_)[e];
        t = (int)((const long long*)tgt_)[e];
    } else {
        c = ((const int*)cur_)[e];
        t = ((const int*)tgt_)[e];
    }
    // 4 features per lane
    uint2 hu = ((const uint2*)(g_Abf + (size_t)c * DD))[lane];
    uint2 tu = ((const uint2*)(g_Abf + (size_t)t * DD))[lane];
    float4 c4 = ((const float4*)(cases + (size_t)e * DD))[lane];
    __nv_bfloat162 h01 = *(__nv_bfloat162*)&hu.x, h23 = *(__nv_bfloat162*)&hu.y;
    __nv_bfloat162 t01 = *(__nv_bfloat162*)&tu.x, t23 = *(__nv_bfloat162*)&tu.y;
    float dx = __bfloat162float(h01.x) + c4.x - __bfloat162float(t01.x);
    float dy = __bfloat162float(h01.y) + c4.y - __bfloat162float(t01.y);
    float dz = __bfloat162float(h23.x) + c4.z - __bfloat162float(t23.x);
    float dw = __bfloat162float(h23.y) + c4.w - __bfloat162float(t23.y);
    float s = dx * dx + dy * dy + dz * dz + dw * dw;
#pragma unroll
    for (int o = 16; o > 0; o >>= 1) s += __shfl_xor_sync(0xffffffffu, s, o);
    if (lane == 0) {
        float v = expf(-sqrtf(s));
        int pos = atomicAdd(&g_cursor[t], 1);
        if (pos < SLOTS)
            g_ent[(size_t)t * SLOTS + pos] = make_float2(__int_as_float(c), v);
    }
}

// ---------------------------------------------------------------------------
// Warp-MMA split-bf16 GEMM1: g_feat[m0:m0+64][:] += W_tile @ B^T
// BM=64, BN=128, BK=64; 256 thr = 8 warps (2m x 4n), warp 32x32.
// grid = 64 M-tiles x 4 K-splits = 256 blocks; 2 CTAs/SM.
// ---------------------------------------------------------------------------
#define PITCHB 144           // bytes per smem row (72 bf16: +8 pad, conflict-free)
#define SM_AH 0
#define SM_AL (64 * PITCHB)
#define SM_BH (2 * 64 * PITCHB)
#define SM_BL (2 * 64 * PITCHB + 128 * PITCHB)
#define SMEM_GEMM (2 * 64 * PITCHB + 2 * 128 * PITCHB)   // 55296 B

__device__ __forceinline__ void mma_bf16(float* c, const uint32_t* a, const uint32_t* b) {
    asm volatile(
        "mma.sync.aligned.m16n8k16.row.col.f32.bf16.bf16.f32 "
        "{%0,%1,%2,%3}, {%4,%5,%6,%7}, {%8,%9}, {%0,%1,%2,%3};"
        : "+f"(c[0]), "+f"(c[1]), "+f"(c[2]), "+f"(c[3])
        : "r"(a[0]), "r"(a[1]), "r"(a[2]), "r"(a[3]), "r"(b[0]), "r"(b[1]));
}

__global__ __launch_bounds__(256, 2)
void gemm_mma_kernel(const float* __restrict__ Amat,
                     const __nv_bfloat16* __restrict__ Bh,
                     const __nv_bfloat16* __restrict__ Bl,
                     float* __restrict__ outacc) {
    extern __shared__ char smem[];
    const int tid = threadIdx.x;
    const int wid = tid >> 5, lane = tid & 31;
    const int warp_m = wid >> 2, warp_n = wid & 3;   // 2 x 4
    const int lr = lane >> 2, lc = lane & 3;
    const int m0 = (blockIdx.x >> 2) * 64;
    const int kbase = (blockIdx.x & 3) * 1024;

    const int a_row = tid >> 4;          // + i*16, i<4 -> rows 0..63
    const int a_c4 = tid & 15;

    float acc[2][4][4];
#pragma unroll
    for (int i = 0; i < 2; i++)
#pragma unroll
        for (int j = 0; j < 4; j++)
#pragma unroll
            for (int q = 0; q < 4; q++) acc[i][j][q] = 0.f;

    for (int ch = 0; ch < 16; ch++) {
        int k0 = kbase + ch * 64;
        float4 av[4];
#pragma unroll
        for (int i = 0; i < 4; i++)
            av[i] = *(const float4*)&Amat[(size_t)(m0 + a_row + i * 16) * NN + k0 + a_c4 * 4];
        uint4 bhv[4], blv[4];
#pragma unroll
        for (int i = 0; i < 4; i++) {
            int idx = tid + i * 256;          // 0..1023
            int n = idx >> 3, q = idx & 7;
            size_t byt = ((size_t)n * NN + k0) * 2 + q * 16;
            bhv[i] = *(const uint4*)((const char*)Bh + byt);
            blv[i] = *(const uint4*)((const char*)Bl + byt);
        }
        if (ch > 0) __syncthreads();
#pragma unroll
        for (int i = 0; i < 4; i++) {
            float4 v = av[i];
            __nv_bfloat16 h0 = __float2bfloat16_rn(v.x);
            __nv_bfloat16 h1 = __float2bfloat16_rn(v.y);
            __nv_bfloat16 h2 = __float2bfloat16_rn(v.z);
            __nv_bfloat16 h3 = __float2bfloat16_rn(v.w);
            __nv_bfloat16 l0 = __float2bfloat16_rn(v.x - __bfloat162float(h0));
            __nv_bfloat16 l1 = __float2bfloat16_rn(v.y - __bfloat162float(h1));
            __nv_bfloat16 l2 = __float2bfloat16_rn(v.z - __bfloat162float(h2));
            __nv_bfloat16 l3 = __float2bfloat16_rn(v.w - __bfloat162float(h3));
            uint2 hp, lp;
            hp.x = ((uint32_t)__bfloat16_as_ushort(h1) << 16) | __bfloat16_as_ushort(h0);
            hp.y = ((uint32_t)__bfloat16_as_ushort(h3) << 16) | __bfloat16_as_ushort(h2);
            lp.x = ((uint32_t)__bfloat16_as_ushort(l1) << 16) | __bfloat16_as_ushort(l0);
            lp.y = ((uint32_t)__bfloat16_as_ushort(l3) << 16) | __bfloat16_as_ushort(l2);
            uint32_t off = (uint32_t)(a_row + i * 16) * PITCHB + a_c4 * 8;
            *(uint2*)(smem + SM_AH + off) = hp;
            *(uint2*)(smem + SM_AL + off) = lp;
        }
#pragma unroll
        for (int i = 0; i < 4; i++) {
            int idx = tid + i * 256;
            int n = idx >> 3, q = idx & 7;
            uint32_t off = (uint32_t)n * PITCHB + q * 16;
            *(uint4*)(smem + SM_BH + off) = bhv[i];
            *(uint4*)(smem + SM_BL + off) = blv[i];
        }
        __syncthreads();
#pragma unroll
        for (int k16 = 0; k16 < 4; k16++) {
            uint32_t a_h[2][4], a_l[2][4];
#pragma unroll
            for (int mt = 0; mt < 2; mt++) {
                uint32_t base = (uint32_t)(warp_m * 32 + mt * 16 + lr) * PITCHB
                                + k16 * 32 + lc * 4;
                a_h[mt][0] = *(const uint32_t*)(smem + SM_AH + base);
                a_h[mt][1] = *(const uint32_t*)(smem + SM_AH + base + 8 * PITCHB);
                a_h[mt][2] = *(const uint32_t*)(smem + SM_AH + base + 16);
                a_h[mt][3] = *(const uint32_t*)(smem + SM_AH + base + 8 * PITCHB + 16);
                a_l[mt][0] = *(const uint32_t*)(smem + SM_AL + base);
                a_l[mt][1] = *(const uint32_t*)(smem + SM_AL + base + 8 * PITCHB);
                a_l[mt][2] = *(const uint32_t*)(smem + SM_AL + base + 16);
                a_l[mt][3] = *(const uint32_t*)(smem + SM_AL + base + 8 * PITCHB + 16);
            }
#pragma unroll
            for (int nt = 0; nt < 4; nt++) {
                uint32_t b_h[2], b_l[2];
                uint32_t base = (uint32_t)(warp_n * 32 + nt * 8 + lr) * PITCHB
                                + k16 * 32 + lc * 4;
                b_h[0] = *(const uint32_t*)(smem + SM_BH + base);
                b_h[1] = *(const uint32_t*)(smem + SM_BH + base + 16);
                b_l[0] = *(const uint32_t*)(smem + SM_BL + base);
                b_l[1] = *(const uint32_t*)(smem + SM_BL + base + 16);
#pragma unroll
                for (int mt = 0; mt < 2; mt++) {
                    mma_bf16(acc[mt][nt], a_h[mt], b_h);
                    mma_bf16(acc[mt][nt], a_h[mt], b_l);
                    mma_bf16(acc[mt][nt], a_l[mt], b_h);
                }
            }
        }
    }
#pragma unroll
    for (int mt = 0; mt < 2; mt++) {
#pragma unroll
        for (int nt = 0; nt < 4; nt++) {
            int row = m0 + warp_m * 32 + mt * 16 + lr;
            int col = warp_n * 32 + nt * 8 + lc * 2;
            atomicAdd(&outacc[(size_t)row * DD + col], acc[mt][nt][0]);
            atomicAdd(&outacc[(size_t)row * DD + col + 1], acc[mt][nt][1]);
            atomicAdd(&outacc[(size_t)(row + 8) * DD + col], acc[mt][nt][2]);
            atomicAdd(&outacc[(size_t)(row + 8) * DD + col + 1], acc[mt][nt][3]);
        }
    }
}

// ---------------------------------------------------------------------------
// fp32 feat -> bf16 copy for SpMM gathers
// ---------------------------------------------------------------------------
__global__ void featbf_kernel() {
    int i = blockIdx.x * 256 + threadIdx.x;   // float4 index, 131072 total
    float4 v = ((const float4*)g_feat)[i];
    uint2 p;
    p.x = ((uint32_t)__bfloat16_as_ushort(__float2bfloat16_rn(v.y)) << 16)
          | __bfloat16_as_ushort(__float2bfloat16_rn(v.x));
    p.y = ((uint32_t)__bfloat16_as_ushort(__float2bfloat16_rn(v.w)) << 16)
          | __bfloat16_as_ushort(__float2bfloat16_rn(v.z));
    ((uint2*)g_featbf)[i] = p;
}

// ---------------------------------------------------------------------------
// SpMM: block per output row t. out[t][:] = (sum val_i * feat[c_i][:]) / (sum
// val_i + eps) + feat[t][:].  feat gathers in bf16 (L2-resident).
// ---------------------------------------------------------------------------
__global__ __launch_bounds__(128)
void spmm_kernel(float* __restrict__ out) {
    __shared__ float2 ch[256];
    int t = blockIdx.x;
    int tid = threadIdx.x;
    int n = g_cursor[t];
    if (n > SLOTS) n = SLOTS;
    const float2* row = g_ent + (size_t)t * SLOTS;
    float acc = 0.f, rsum = 0.f;
    for (int base = 0; base < n; base += 256) {
        int rem = n - base;
        if (tid < rem) ch[tid] = row[base + tid];
        if (tid + 128 < rem) ch[tid + 128] = row[base + tid + 128];
        __syncthreads();
        int lim = rem < 256 ? rem : 256;
#pragma unroll 4
        for (int j = 0; j < lim; j++) {
            float2 ev = ch[j];
            int c = __float_as_int(ev.x);
            rsum += ev.y;
            acc += ev.y * __bfloat162float(g_featbf[c * DD + tid]);
        }
        __syncthreads();
    }
    out[(size_t)t * DD + tid] = acc / (rsum + EPS) + g_feat[(size_t)t * DD + tid];
}

// ---------------------------------------------------------------------------
extern "C" void kernel_launch(void* const* d_in, const int* in_sizes, int n_in,
                              void* d_out, int out_size) {
    const void* cur = d_in[0];
    const void* tgt = d_in[1];
    const float* A = (const float*)d_in[2];
    const float* cases = (const float*)d_in[3];
    const float* W = (const float*)d_in[4];
    float* out = (float*)d_out;
    int E = in_sizes[3] / DD;

    cudaFuncSetAttribute(gemm_mma_kernel,
                         cudaFuncAttributeMaxDynamicSharedMemorySize, SMEM_GEMM);

    float* p_feat;
    int* p_cursor;
    __nv_bfloat16 *p_Bh, *p_Bl;
    cudaGetSymbolAddress((void**)&p_feat, g_feat);
    cudaGetSymbolAddress((void**)&p_cursor, g_cursor);
    cudaGetSymbolAddress((void**)&p_Bh, g_Bh);
    cudaGetSymbolAddress((void**)&p_Bl, g_Bl);

    cudaMemsetAsync(p_feat, 0, (size_t)NN * DD * sizeof(float));
    cudaMemsetAsync(p_cursor, 0, NN * sizeof(int));

    detect_kernel<<<1, 32>>>((const unsigned int*)cur);
    prep_kernel<<<dim3(NN / 32, DD / 32), dim3(32, 8)>>>(A);
    edge_kernel<<<(E + 7) / 8, dim3(32, 8)>>>(cur, tgt, cases, E);
    gemm_mma_kernel<<<256, 256, SMEM_GEMM>>>(W, p_Bh, p_Bl, p_feat);
    featbf_kernel<<<512, 256>>>();
    spmm_kernel<<<NN, 128>>>(out);
}

// round 7
// speedup vs baseline: 3.5062x; 1.0632x over previous
#include <cuda_runtime.h>
#include <cuda_bf16.h>
#include <cstdint>
#include <cstddef>

#define NN 4096
#define DD 128
#define EPS 1e-12f
#define SLOTS 512            // per-row edge slots (mean 244, 17-sigma safe)

#define NGEMM 256            // gemm tile-blocks (64 M-tiles x 4 K-splits)
#define GRID_FUSED 2048      // total blocks; 1792 edge blocks

// ---------------- scratch (__device__ globals; no allocs allowed) ----------
__device__ float g_feat[NN * DD];                       // W @ activities (fp32)
__device__ __nv_bfloat16 g_featbf[NN * DD];             // bf16 copy for SpMM gathers
__device__ __nv_bfloat16 g_Abf[NN * DD];                // activities bf16 (edge gathers)
__device__ __nv_bfloat16 g_Bh[DD * NN], g_Bl[DD * NN];  // activities^T split [N][K]
__device__ float2 g_ent[(size_t)NN * SLOTS];            // (col,val) per row, 16 MB
__device__ int g_cursor[NN];
__device__ int g_is64;

// ---------------------------------------------------------------------------
__global__ void detect_kernel(const unsigned int* __restrict__ w) {
    if (threadIdx.x == 0) {
        int is64 = 1;
        for (int i = 0; i < 64; i++)
            if (w[2 * i + 1] != 0u) { is64 = 0; break; }
        g_is64 = is64;
    }
}

// ---------------------------------------------------------------------------
// prep: A [4096,128] fp32 -> g_Bh/g_Bl [128][4096] (transposed split, GEMM B)
//                         -> g_Abf [4096,128] bf16 (edge gathers)
// ---------------------------------------------------------------------------
__global__ void prep_kernel(const float* __restrict__ src) {
    __shared__ float tile[32][33];
    int k0 = blockIdx.x * 32, n0 = blockIdx.y * 32;
    int tx = threadIdx.x, ty = threadIdx.y;
#pragma unroll
    for (int i = 0; i < 4; i++) {
        size_t idx = (size_t)(k0 + ty + i * 8) * DD + n0 + tx;
        float v = src[idx];
        tile[ty + i * 8][tx] = v;
        g_Abf[idx] = __float2bfloat16_rn(v);
    }
    __syncthreads();
#pragma unroll
    for (int i = 0; i < 4; i++) {
        float x = tile[tx][ty + i * 8];
        __nv_bfloat16 h = __float2bfloat16_rn(x);
        __nv_bfloat16 l = __float2bfloat16_rn(x - __bfloat162float(h));
        size_t o = (size_t)(n0 + ty + i * 8) * NN + k0 + tx;
        g_Bh[o] = h;
        g_Bl[o] = l;
    }
}

// ---------------------------------------------------------------------------
#define PITCHB 144           // bytes per smem row (72 bf16: +8 pad, conflict-free)
#define SM_AH 0
#define SM_AL (64 * PITCHB)
#define SM_BH (2 * 64 * PITCHB)
#define SM_BL (2 * 64 * PITCHB + 128 * PITCHB)
#define SMEM_GEMM (2 * 64 * PITCHB + 2 * 128 * PITCHB)   // 55296 B

__device__ __forceinline__ void mma_bf16(float* c, const uint32_t* a, const uint32_t* b) {
    asm volatile(
        "mma.sync.aligned.m16n8k16.row.col.f32.bf16.bf16.f32 "
        "{%0,%1,%2,%3}, {%4,%5,%6,%7}, {%8,%9}, {%0,%1,%2,%3};"
        : "+f"(c[0]), "+f"(c[1]), "+f"(c[2]), "+f"(c[3])
        : "r"(a[0]), "r"(a[1]), "r"(a[2]), "r"(a[3]), "r"(b[0]), "r"(b[1]));
}

// ---------------------------------------------------------------------------
// Gemm tile body: g_feat[m0:m0+64][:] += W_tile @ B^T  (split-K partials)
// ---------------------------------------------------------------------------
__device__ __forceinline__ void gemm_tile(char* smem, int tile,
                                          const float* __restrict__ Amat,
                                          const __nv_bfloat16* __restrict__ Bh,
                                          const __nv_bfloat16* __restrict__ Bl,
                                          float* __restrict__ outacc) {
    const int tid = threadIdx.x;
    const int wid = tid >> 5, lane = tid & 31;
    const int warp_m = wid >> 2, warp_n = wid & 3;   // 2 x 4
    const int lr = lane >> 2, lc = lane & 3;
    const int m0 = (tile >> 2) * 64;
    const int kbase = (tile & 3) * 1024;

    const int a_row = tid >> 4;
    const int a_c4 = tid & 15;

    float acc[2][4][4];
#pragma unroll
    for (int i = 0; i < 2; i++)
#pragma unroll
        for (int j = 0; j < 4; j++)
#pragma unroll
            for (int q = 0; q < 4; q++) acc[i][j][q] = 0.f;

    for (int ch = 0; ch < 16; ch++) {
        int k0 = kbase + ch * 64;
        float4 av[4];
#pragma unroll
        for (int i = 0; i < 4; i++)
            av[i] = *(const float4*)&Amat[(size_t)(m0 + a_row + i * 16) * NN + k0 + a_c4 * 4];
        uint4 bhv[4], blv[4];
#pragma unroll
        for (int i = 0; i < 4; i++) {
            int idx = tid + i * 256;
            int n = idx >> 3, q = idx & 7;
            size_t byt = ((size_t)n * NN + k0) * 2 + q * 16;
            bhv[i] = *(const uint4*)((const char*)Bh + byt);
            blv[i] = *(const uint4*)((const char*)Bl + byt);
        }
        if (ch > 0) __syncthreads();
#pragma unroll
        for (int i = 0; i < 4; i++) {
            float4 v = av[i];
            __nv_bfloat16 h0 = __float2bfloat16_rn(v.x);
            __nv_bfloat16 h1 = __float2bfloat16_rn(v.y);
            __nv_bfloat16 h2 = __float2bfloat16_rn(v.z);
            __nv_bfloat16 h3 = __float2bfloat16_rn(v.w);
            __nv_bfloat16 l0 = __float2bfloat16_rn(v.x - __bfloat162float(h0));
            __nv_bfloat16 l1 = __float2bfloat16_rn(v.y - __bfloat162float(h1));
            __nv_bfloat16 l2 = __float2bfloat16_rn(v.z - __bfloat162float(h2));
            __nv_bfloat16 l3 = __float2bfloat16_rn(v.w - __bfloat162float(h3));
            uint2 hp, lp;
            hp.x = ((uint32_t)__bfloat16_as_ushort(h1) << 16) | __bfloat16_as_ushort(h0);
            hp.y = ((uint32_t)__bfloat16_as_ushort(h3) << 16) | __bfloat16_as_ushort(h2);
            lp.x = ((uint32_t)__bfloat16_as_ushort(l1) << 16) | __bfloat16_as_ushort(l0);
            lp.y = ((uint32_t)__bfloat16_as_ushort(l3) << 16) | __bfloat16_as_ushort(l2);
            uint32_t off = (uint32_t)(a_row + i * 16) * PITCHB + a_c4 * 8;
            *(uint2*)(smem + SM_AH + off) = hp;
            *(uint2*)(smem + SM_AL + off) = lp;
        }
#pragma unroll
        for (int i = 0; i < 4; i++) {
            int idx = tid + i * 256;
            int n = idx >> 3, q = idx & 7;
            uint32_t off = (uint32_t)n * PITCHB + q * 16;
            *(uint4*)(smem + SM_BH + off) = bhv[i];
            *(uint4*)(smem + SM_BL + off) = blv[i];
        }
        __syncthreads();
#pragma unroll
        for (int k16 = 0; k16 < 4; k16++) {
            uint32_t a_h[2][4], a_l[2][4];
#pragma unroll
            for (int mt = 0; mt < 2; mt++) {
                uint32_t base = (uint32_t)(warp_m * 32 + mt * 16 + lr) * PITCHB
                                + k16 * 32 + lc * 4;
                a_h[mt][0] = *(const uint32_t*)(smem + SM_AH + base);
                a_h[mt][1] = *(const uint32_t*)(smem + SM_AH + base + 8 * PITCHB);
                a_h[mt][2] = *(const uint32_t*)(smem + SM_AH + base + 16);
                a_h[mt][3] = *(const uint32_t*)(smem + SM_AH + base + 8 * PITCHB + 16);
                a_l[mt][0] = *(const uint32_t*)(smem + SM_AL + base);
                a_l[mt][1] = *(const uint32_t*)(smem + SM_AL + base + 8 * PITCHB);
                a_l[mt][2] = *(const uint32_t*)(smem + SM_AL + base + 16);
                a_l[mt][3] = *(const uint32_t*)(smem + SM_AL + base + 8 * PITCHB + 16);
            }
#pragma unroll
            for (int nt = 0; nt < 4; nt++) {
                uint32_t b_h[2], b_l[2];
                uint32_t base = (uint32_t)(warp_n * 32 + nt * 8 + lr) * PITCHB
                                + k16 * 32 + lc * 4;
                b_h[0] = *(const uint32_t*)(smem + SM_BH + base);
                b_h[1] = *(const uint32_t*)(smem + SM_BH + base + 16);
                b_l[0] = *(const uint32_t*)(smem + SM_BL + base);
                b_l[1] = *(const uint32_t*)(smem + SM_BL + base + 16);
#pragma unroll
                for (int mt = 0; mt < 2; mt++) {
                    mma_bf16(acc[mt][nt], a_h[mt], b_h);
                    mma_bf16(acc[mt][nt], a_h[mt], b_l);
                    mma_bf16(acc[mt][nt], a_l[mt], b_h);
                }
            }
        }
    }
#pragma unroll
    for (int mt = 0; mt < 2; mt++) {
#pragma unroll
        for (int nt = 0; nt < 4; nt++) {
            int row = (tile >> 2) * 64 + warp_m * 32 + mt * 16 + lr;
            int col = warp_n * 32 + nt * 8 + lc * 2;
            atomicAdd(&outacc[(size_t)row * DD + col], acc[mt][nt][0]);
            atomicAdd(&outacc[(size_t)row * DD + col + 1], acc[mt][nt][1]);
            atomicAdd(&outacc[(size_t)(row + 8) * DD + col], acc[mt][nt][2]);
            atomicAdd(&outacc[(size_t)(row + 8) * DD + col + 1], acc[mt][nt][3]);
        }
    }
}

// ---------------------------------------------------------------------------
// Edge strip body: warp processes 4 edges per iteration.
//   - cursor atomics issued by lanes 0-3 BEFORE feature math (hide 318 cyc)
//   - 12 independent vector loads in flight (MLP 12)
// ---------------------------------------------------------------------------
__device__ __forceinline__ void edge_strip(int rank,
                                           const void* __restrict__ cur_,
                                           const void* __restrict__ tgt_,
                                           const float* __restrict__ cases,
                                           int E) {
    const int wid = threadIdx.x >> 5, lane = threadIdx.x & 31;
    const int NW = (GRID_FUSED - NGEMM) * 8;
    const int strip = (E + NW - 1) / NW;
    const int wg = rank * 8 + wid;
    int wstart = wg * strip;
    int wend = wstart + strip;
    if (wend > E) wend = E;
    const int is64 = g_is64;
    const long long* cur64 = (const long long*)cur_;
    const long long* tgt64 = (const long long*)tgt_;
    const int* cur32 = (const int*)cur_;
    const int* tgt32 = (const int*)tgt_;

    for (int e0 = wstart; e0 < wend; e0 += 4) {
        int nb = wend - e0;
        if (nb > 4) nb = 4;
        int c[4], t[4];
#pragma unroll
        for (int i = 0; i < 4; i++) {
            int e = (i < nb) ? e0 + i : e0;
            if (is64) {
                c[i] = (int)__ldg(&cur64[e]);
                t[i] = (int)__ldg(&tgt64[e]);
            } else {
                c[i] = __ldg(&cur32[e]);
                t[i] = __ldg(&tgt32[e]);
            }
        }
        // my-lane copies (avoid dynamic register indexing)
        int tm = (lane == 0) ? t[0] : (lane == 1) ? t[1] : (lane == 2) ? t[2] : t[3];
        int cm = (lane == 0) ? c[0] : (lane == 1) ? c[1] : (lane == 2) ? c[2] : c[3];
        // early atomics (lanes 0..nb-1)
        int pos = 0;
        if (lane < nb) pos = atomicAdd(&g_cursor[tm], 1);
        // feature loads: all independent
        uint2 hu[4], tu[4];
        float4 cv[4];
#pragma unroll
        for (int i = 0; i < 4; i++) {
            hu[i] = __ldg(&((const uint2*)(g_Abf + (size_t)c[i] * DD))[lane]);
            tu[i] = __ldg(&((const uint2*)(g_Abf + (size_t)t[i] * DD))[lane]);
            cv[i] = __ldg(&((const float4*)(cases + (size_t)(e0 + ((i < nb) ? i : 0)) * DD))[lane]);
        }
        float sred[4];
#pragma unroll
        for (int i = 0; i < 4; i++) {
            __nv_bfloat162 h01 = *(__nv_bfloat162*)&hu[i].x, h23 = *(__nv_bfloat162*)&hu[i].y;
            __nv_bfloat162 t01 = *(__nv_bfloat162*)&tu[i].x, t23 = *(__nv_bfloat162*)&tu[i].y;
            float dx = __bfloat162float(h01.x) + cv[i].x - __bfloat162float(t01.x);
            float dy = __bfloat162float(h01.y) + cv[i].y - __bfloat162float(t01.y);
            float dz = __bfloat162float(h23.x) + cv[i].z - __bfloat162float(t23.x);
            float dw = __bfloat162float(h23.y) + cv[i].w - __bfloat162float(t23.y);
            float s = dx * dx + dy * dy + dz * dz + dw * dw;
#pragma unroll
            for (int o = 16; o > 0; o >>= 1) s += __shfl_xor_sync(0xffffffffu, s, o);
            sred[i] = s;
        }
        if (lane < nb && pos < SLOTS) {
            float sm = (lane == 0) ? sred[0] : (lane == 1) ? sred[1]
                       : (lane == 2) ? sred[2] : sred[3];
            float v = expf(-sqrtf(sm));
            g_ent[(size_t)tm * SLOTS + pos] = make_float2(__int_as_float(cm), v);
        }
    }
}

// ---------------------------------------------------------------------------
// Fused kernel: blocks 0..511 alternate gemm/edge (1 gemm + 1 edge per SM
// slot-pair during the first wave); blocks 512+ are edge strips.
// ---------------------------------------------------------------------------
__global__ __launch_bounds__(256, 2)
void fused_kernel(const float* __restrict__ Wm,
                  const __nv_bfloat16* __restrict__ Bh,
                  const __nv_bfloat16* __restrict__ Bl,
                  float* __restrict__ outacc,
                  const void* __restrict__ cur_,
                  const void* __restrict__ tgt_,
                  const float* __restrict__ cases,
                  int E) {
    extern __shared__ char smem[];
    int b = blockIdx.x;
    if (b < 512 && (b & 1) == 0) {
        gemm_tile(smem, b >> 1, Wm, Bh, Bl, outacc);
    } else {
        int rank = (b < 512) ? (b >> 1) : (b - NGEMM);
        edge_strip(rank, cur_, tgt_, cases, E);
    }
}

// ---------------------------------------------------------------------------
// fp32 feat -> bf16 copy for SpMM gathers
// ---------------------------------------------------------------------------
__global__ void featbf_kernel() {
    int i = blockIdx.x * 256 + threadIdx.x;
    float4 v = ((const float4*)g_feat)[i];
    uint2 p;
    p.x = ((uint32_t)__bfloat16_as_ushort(__float2bfloat16_rn(v.y)) << 16)
          | __bfloat16_as_ushort(__float2bfloat16_rn(v.x));
    p.y = ((uint32_t)__bfloat16_as_ushort(__float2bfloat16_rn(v.w)) << 16)
          | __bfloat16_as_ushort(__float2bfloat16_rn(v.z));
    ((uint2*)g_featbf)[i] = p;
}

// ---------------------------------------------------------------------------
// SpMM: block per output row t. out[t][:] = (sum val_i * feat[c_i][:]) /
// (sum val_i + eps) + feat[t][:].  feat gathers in bf16 (L2-resident).
// ---------------------------------------------------------------------------
__global__ __launch_bounds__(128)
void spmm_kernel(float* __restrict__ out) {
    __shared__ float2 ch[256];
    int t = blockIdx.x;
    int tid = threadIdx.x;
    int n = g_cursor[t];
    if (n > SLOTS) n = SLOTS;
    const float2* row = g_ent + (size_t)t * SLOTS;
    float acc = 0.f, rsum = 0.f;
    for (int base = 0; base < n; base += 256) {
        int rem = n - base;
        if (tid < rem) ch[tid] = row[base + tid];
        if (tid + 128 < rem) ch[tid + 128] = row[base + tid + 128];
        __syncthreads();
        int lim = rem < 256 ? rem : 256;
#pragma unroll 8
        for (int j = 0; j < lim; j++) {
            float2 ev = ch[j];
            int c = __float_as_int(ev.x);
            rsum += ev.y;
            acc += ev.y * __bfloat162float(g_featbf[c * DD + tid]);
        }
        __syncthreads();
    }
    out[(size_t)t * DD + tid] = acc / (rsum + EPS) + g_feat[(size_t)t * DD + tid];
}

// ---------------------------------------------------------------------------
extern "C" void kernel_launch(void* const* d_in, const int* in_sizes, int n_in,
                              void* d_out, int out_size) {
    const void* cur = d_in[0];
    const void* tgt = d_in[1];
    const float* A = (const float*)d_in[2];
    const float* cases = (const float*)d_in[3];
    const float* W = (const float*)d_in[4];
    float* out = (float*)d_out;
    int E = in_sizes[3] / DD;

    cudaFuncSetAttribute(fused_kernel,
                         cudaFuncAttributeMaxDynamicSharedMemorySize, SMEM_GEMM);

    float* p_feat;
    int* p_cursor;
    __nv_bfloat16 *p_Bh, *p_Bl;
    cudaGetSymbolAddress((void**)&p_feat, g_feat);
    cudaGetSymbolAddress((void**)&p_cursor, g_cursor);
    cudaGetSymbolAddress((void**)&p_Bh, g_Bh);
    cudaGetSymbolAddress((void**)&p_Bl, g_Bl);

    cudaMemsetAsync(p_feat, 0, (size_t)NN * DD * sizeof(float));
    cudaMemsetAsync(p_cursor, 0, NN * sizeof(int));

    detect_kernel<<<1, 32>>>((const unsigned int*)cur);
    prep_kernel<<<dim3(NN / 32, DD / 32), dim3(32, 8)>>>(A);
    fused_kernel<<<GRID_FUSED, 256, SMEM_GEMM>>>(W, p_Bh, p_Bl, p_feat,
                                                 cur, tgt, cases, E);
    featbf_kernel<<<512, 256>>>();
    spmm_kernel<<<NN, 128>>>(out);
}